// round 3
// baseline (speedup 1.0000x reference)
#include <cuda_runtime.h>
#include <cstdint>

// ---------------------------------------------------------------------------
// QuantizedTokenizer: VQ-VAE tokenizer, fp32 with packed FFMA2 (fma.rn.f32x2).
//   B=32, Q=1024, H=1024, HR=512, C=4096, N = B*Q = 32768
// Outputs (flattened, float32, reference return order):
//   recon        [N,H]   @ 0
//   quantized_st [N,HR]  @ 33554432
//   token_index  [N]     @ 50331648 (as float)
//   commit_loss  [1]     @ 50364416
// ---------------------------------------------------------------------------

constexpr int NTOK = 32768;
constexpr int HDIM = 1024;
constexpr int HR   = 512;
constexpr int CNUM = 4096;

constexpr int BM = 128, BN = 128, BK = 16, NTHR = 256;

// Scratch (no allocation allowed -> __device__ globals)
__device__ float  g_h [(size_t)NTOK * HDIM];
__device__ float  g_z [(size_t)NTOK * HR];
__device__ float  g_h2[(size_t)NTOK * HDIM];
__device__ int    g_idx[NTOK];
__device__ float  g_cnorm[CNUM];
__device__ double g_part[NTOK];

// ---------------------------------------------------------------------------
// codebook row norms: ||c||^2
// ---------------------------------------------------------------------------
__global__ void cnorm_kernel(const float* __restrict__ cb, float* __restrict__ cn) {
    int c = blockIdx.x;
    const float* row = cb + (size_t)c * HR;
    float s = 0.f;
    for (int k = threadIdx.x; k < HR; k += 128) { float v = row[k]; s += v * v; }
    __shared__ float sh[128];
    sh[threadIdx.x] = s; __syncthreads();
    for (int o = 64; o > 0; o >>= 1) {
        if (threadIdx.x < o) sh[threadIdx.x] += sh[threadIdx.x + o];
        __syncthreads();
    }
    if (threadIdx.x == 0) cn[c] = sh[0];
}

// ---------------------------------------------------------------------------
// Packed f32x2 helpers (sm_103a FFMA2 path; bit-identical to scalar FFMA).
// ---------------------------------------------------------------------------
__device__ __forceinline__ unsigned long long splat_f32x2(float a) {
    unsigned long long r;
    asm("mov.b64 %0, {%1, %1};" : "=l"(r) : "f"(a));
    return r;
}
__device__ __forceinline__ void fma_f32x2(unsigned long long& acc,
                                          unsigned long long a, unsigned long long b) {
    asm("fma.rn.f32x2 %0, %1, %2, %0;" : "+l"(acc) : "l"(a), "l"(b));
}
__device__ __forceinline__ void unpack_f32x2(unsigned long long v, float& lo, float& hi) {
    asm("mov.b64 {%0, %1}, %2;" : "=f"(lo), "=f"(hi) : "l"(v));
}

// ---------------------------------------------------------------------------
// Micro-kernel (shared by sgemm and dist_argmin).
// Thread (ty 0..15, tx 0..15) owns rows {ty*4+i, 64+ty*4+i} and
// cols {tx*4+j, 64+tx*4+j}. All smem reads are LDS.128; B pairs are taken
// directly as f32x2 lanes; inner product runs on FFMA2 (32 instr/k-step).
// acc2[i][jp]: rows i (0..7 as above), col-pair jp -> cols
//   jp<2 : tx*4 + 2*jp + {0,1} ; jp>=2 : 64 + tx*4 + 2*(jp-2) + {0,1}
// ---------------------------------------------------------------------------
struct Frag { float4 a0, a1, b0, b1; };  // gmem staging registers

__device__ __forceinline__ void mm_step(const float (*As)[BM], const float (*Bs)[BN],
                                        int ty, int tx,
                                        unsigned long long acc2[8][4]) {
    #pragma unroll
    for (int k = 0; k < BK; k++) {
        float a[8];
        *reinterpret_cast<float4*>(&a[0]) = *reinterpret_cast<const float4*>(&As[k][ty * 4]);
        *reinterpret_cast<float4*>(&a[4]) = *reinterpret_cast<const float4*>(&As[k][64 + ty * 4]);
        unsigned long long b2[4];
        {
            ulonglong2 t0 = *reinterpret_cast<const ulonglong2*>(&Bs[k][tx * 4]);
            ulonglong2 t1 = *reinterpret_cast<const ulonglong2*>(&Bs[k][64 + tx * 4]);
            b2[0] = t0.x; b2[1] = t0.y; b2[2] = t1.x; b2[3] = t1.y;
        }
        #pragma unroll
        for (int i = 0; i < 8; i++) {
            unsigned long long ap = splat_f32x2(a[i]);
            #pragma unroll
            for (int jp = 0; jp < 4; jp++)
                fma_f32x2(acc2[i][jp], ap, b2[jp]);
        }
    }
}

// A-tile gmem load: 128 rows x 16 k, float4 along K; 2 vec4/thread.
__device__ __forceinline__ void load_a(const float* __restrict__ A, int row0, int K,
                                       int k0, int tid, float4& v0, float4& v1) {
    int r = tid >> 2, c = (tid & 3) * 4;
    v0 = *reinterpret_cast<const float4*>(&A[(size_t)(row0 + r) * K + k0 + c]);
    v1 = *reinterpret_cast<const float4*>(&A[(size_t)(row0 + r + 64) * K + k0 + c]);
}
__device__ __forceinline__ void store_a(float (*As)[BM], int tid, float4 v0, float4 v1) {
    int r = tid >> 2, c = (tid & 3) * 4;
    As[c + 0][r] = v0.x; As[c + 1][r] = v0.y; As[c + 2][r] = v0.z; As[c + 3][r] = v0.w;
    As[c + 0][r + 64] = v1.x; As[c + 1][r + 64] = v1.y;
    As[c + 2][r + 64] = v1.z; As[c + 3][r + 64] = v1.w;
}

// B-tile (row-major W[K,N]) gmem load: 16 k x 128 cols, float4 along N.
__device__ __forceinline__ void load_b_rowmajor(const float* __restrict__ W, int col0, int N,
                                                int k0, int tid, float4& v0, float4& v1) {
    int r = tid >> 5, c = (tid & 31) * 4;
    v0 = *reinterpret_cast<const float4*>(&W[(size_t)(k0 + r) * N + col0 + c]);
    v1 = *reinterpret_cast<const float4*>(&W[(size_t)(k0 + r + 8) * N + col0 + c]);
}
__device__ __forceinline__ void store_b_rowmajor(float (*Bs)[BN], int tid, float4 v0, float4 v1) {
    int r = tid >> 5, c = (tid & 31) * 4;
    *reinterpret_cast<float4*>(&Bs[r][c]) = v0;
    *reinterpret_cast<float4*>(&Bs[r + 8][c]) = v1;
}

// Codebook tile (CB[C,HR], need Bs[k][c] = CB[c0+c][k0+k]): transpose on store.
__device__ __forceinline__ void load_b_trans(const float* __restrict__ CB, int c0,
                                             int k0, int tid, float4& v0, float4& v1) {
    int r = tid >> 2, c = (tid & 3) * 4;   // r = codeword in tile, c = k offset
    v0 = *reinterpret_cast<const float4*>(&CB[(size_t)(c0 + r) * HR + k0 + c]);
    v1 = *reinterpret_cast<const float4*>(&CB[(size_t)(c0 + r + 64) * HR + k0 + c]);
}
__device__ __forceinline__ void store_b_trans(float (*Bs)[BN], int tid, float4 v0, float4 v1) {
    int r = tid >> 2, c = (tid & 3) * 4;
    Bs[c + 0][r] = v0.x; Bs[c + 1][r] = v0.y; Bs[c + 2][r] = v0.z; Bs[c + 3][r] = v0.w;
    Bs[c + 0][r + 64] = v1.x; Bs[c + 1][r + 64] = v1.y;
    Bs[c + 2][r + 64] = v1.z; Bs[c + 3][r + 64] = v1.w;
}

// ---------------------------------------------------------------------------
// SGEMM: C = act(A[M,K] @ W[K,N] + bias), 128x128x16, double-buffered smem.
// ---------------------------------------------------------------------------
template <bool RELU>
__global__ void __launch_bounds__(NTHR, 2)
sgemm_bias(const float* __restrict__ A, const float* __restrict__ W,
           const float* __restrict__ bias, float* __restrict__ C,
           int M, int N, int K) {
    __shared__ __align__(16) float As[2][BK][BM];
    __shared__ __align__(16) float Bs[2][BK][BN];

    const int tid  = threadIdx.x;
    const int tx   = tid & 15;
    const int ty   = tid >> 4;
    const int row0 = blockIdx.y * BM;
    const int col0 = blockIdx.x * BN;

    unsigned long long acc2[8][4] = {};   // zero bits == (0.f, 0.f)
    Frag f;

    load_a(A, row0, K, 0, tid, f.a0, f.a1);
    load_b_rowmajor(W, col0, N, 0, tid, f.b0, f.b1);
    store_a(As[0], tid, f.a0, f.a1);
    store_b_rowmajor(Bs[0], tid, f.b0, f.b1);
    __syncthreads();

    int buf = 0;
    for (int k0 = BK; k0 <= K; k0 += BK) {
        if (k0 < K) {
            load_a(A, row0, K, k0, tid, f.a0, f.a1);
            load_b_rowmajor(W, col0, N, k0, tid, f.b0, f.b1);
        }
        mm_step(As[buf], Bs[buf], ty, tx, acc2);
        if (k0 < K) {
            store_a(As[buf ^ 1], tid, f.a0, f.a1);
            store_b_rowmajor(Bs[buf ^ 1], tid, f.b0, f.b1);
            __syncthreads();
            buf ^= 1;
        }
    }

    #pragma unroll
    for (int ih = 0; ih < 2; ih++) {
        #pragma unroll
        for (int i = 0; i < 4; i++) {
            int r = row0 + ih * 64 + ty * 4 + i;
            #pragma unroll
            for (int jh = 0; jh < 2; jh++) {
                int c = col0 + jh * 64 + tx * 4;
                float4 bv = *reinterpret_cast<const float4*>(&bias[c]);
                float4 v;
                unpack_f32x2(acc2[ih * 4 + i][jh * 2 + 0], v.x, v.y);
                unpack_f32x2(acc2[ih * 4 + i][jh * 2 + 1], v.z, v.w);
                v.x += bv.x; v.y += bv.y; v.z += bv.z; v.w += bv.w;
                if (RELU) {
                    v.x = fmaxf(v.x, 0.f); v.y = fmaxf(v.y, 0.f);
                    v.z = fmaxf(v.z, 0.f); v.w = fmaxf(v.w, 0.f);
                }
                *reinterpret_cast<float4*>(&C[(size_t)r * N + c]) = v;
            }
        }
    }
}

// ---------------------------------------------------------------------------
// Distance GEMM + fused argmin.
// d[n,c] = ||cb_c||^2 - 2 z_n.cb_c ; idx = argmin_c (first index on ties).
// Packed key (orderable_f32(d) << 32 | c) -> min == argmin with jnp tie-break.
// ---------------------------------------------------------------------------
__device__ __forceinline__ unsigned int f32_orderable(float f) {
    unsigned int u = __float_as_uint(f);
    return (u & 0x80000000u) ? ~u : (u | 0x80000000u);
}

__global__ void __launch_bounds__(NTHR, 2)
dist_argmin(const float* __restrict__ Z, const float* __restrict__ CB,
            const float* __restrict__ cn, int* __restrict__ out_idx) {
    __shared__ __align__(16) float As[2][BK][BM];
    __shared__ __align__(16) float Bs[2][BK][BN];
    __shared__ unsigned long long best[BM];

    const int tid  = threadIdx.x;
    const int tx   = tid & 15;
    const int ty   = tid >> 4;
    const int row0 = blockIdx.x * BM;

    for (int i = tid; i < BM; i += NTHR) best[i] = 0xFFFFFFFFFFFFFFFFull;

    unsigned long long mykey[8];
    #pragma unroll
    for (int i = 0; i < 8; i++) mykey[i] = 0xFFFFFFFFFFFFFFFFull;

    for (int c0 = 0; c0 < CNUM; c0 += BN) {
        unsigned long long acc2[8][4] = {};
        Frag f;
        load_a(Z, row0, HR, 0, tid, f.a0, f.a1);
        load_b_trans(CB, c0, 0, tid, f.b0, f.b1);
        __syncthreads();                       // protect prev iter's smem reads
        store_a(As[0], tid, f.a0, f.a1);
        store_b_trans(Bs[0], tid, f.b0, f.b1);
        __syncthreads();

        int buf = 0;
        for (int k0 = BK; k0 <= HR; k0 += BK) {
            if (k0 < HR) {
                load_a(Z, row0, HR, k0, tid, f.a0, f.a1);
                load_b_trans(CB, c0, k0, tid, f.b0, f.b1);
            }
            mm_step(As[buf], Bs[buf], ty, tx, acc2);
            if (k0 < HR) {
                store_a(As[buf ^ 1], tid, f.a0, f.a1);
                store_b_trans(Bs[buf ^ 1], tid, f.b0, f.b1);
                __syncthreads();
                buf ^= 1;
            }
        }

        // fold this 128-codeword tile into per-thread running min
        #pragma unroll
        for (int jh = 0; jh < 2; jh++) {
            #pragma unroll
            for (int jp = 0; jp < 2; jp++) {
                int c = c0 + jh * 64 + tx * 4 + jp * 2;
                float cn0 = __ldg(&cn[c]);
                float cn1 = __ldg(&cn[c + 1]);
                #pragma unroll
                for (int i = 0; i < 8; i++) {
                    float d0, d1;
                    unpack_f32x2(acc2[i][jh * 2 + jp], d0, d1);
                    d0 = cn0 - 2.0f * d0;
                    d1 = cn1 - 2.0f * d1;
                    unsigned long long k0v =
                        ((unsigned long long)f32_orderable(d0) << 32) | (unsigned)c;
                    unsigned long long k1v =
                        ((unsigned long long)f32_orderable(d1) << 32) | (unsigned)(c + 1);
                    if (k0v < mykey[i]) mykey[i] = k0v;
                    if (k1v < mykey[i]) mykey[i] = k1v;
                }
            }
        }
    }

    __syncthreads();                           // best[] init + last smem reads done
    #pragma unroll
    for (int ih = 0; ih < 2; ih++)
        #pragma unroll
        for (int i = 0; i < 4; i++)
            atomicMin(&best[ih * 64 + ty * 4 + i], mykey[ih * 4 + i]);
    __syncthreads();
    for (int i = tid; i < BM; i += NTHR)
        out_idx[row0 + i] = (int)(best[i] & 0xFFFFFFFFu);
}

// ---------------------------------------------------------------------------
// Gather quantized = codebook[idx] -> out; per-token commit partial (double)
// ---------------------------------------------------------------------------
__global__ void quant_commit(const float* __restrict__ Z, const float* __restrict__ CB,
                             const int* __restrict__ idx, float* __restrict__ out_q,
                             double* __restrict__ part) {
    int t = blockIdx.x;
    const float* cbrow = CB + (size_t)idx[t] * HR;
    const float* zrow  = Z + (size_t)t * HR;
    float* qrow        = out_q + (size_t)t * HR;
    double s = 0.0;
    for (int k = threadIdx.x; k < HR; k += 128) {
        float q = cbrow[k];
        float d = zrow[k] - q;
        qrow[k] = q;
        s += (double)d * (double)d;
    }
    __shared__ double sh[128];
    sh[threadIdx.x] = s; __syncthreads();
    for (int o = 64; o > 0; o >>= 1) {
        if (threadIdx.x < o) sh[threadIdx.x] += sh[threadIdx.x + o];
        __syncthreads();
    }
    if (threadIdx.x == 0) part[t] = sh[0];
}

__global__ void commit_reduce(const double* __restrict__ part, float* __restrict__ out) {
    __shared__ double sh[256];
    double s = 0.0;
    for (int i = threadIdx.x; i < NTOK; i += 256) s += part[i];
    sh[threadIdx.x] = s; __syncthreads();
    for (int o = 128; o > 0; o >>= 1) {
        if (threadIdx.x < o) sh[threadIdx.x] += sh[threadIdx.x + o];
        __syncthreads();
    }
    if (threadIdx.x == 0)
        out[0] = (float)(0.25 * sh[0] / ((double)NTOK * (double)HR));
}

__global__ void write_indices(const int* __restrict__ idx, float* __restrict__ out) {
    int i = blockIdx.x * blockDim.x + threadIdx.x;
    if (i < NTOK) out[i] = (float)idx[i];
}

// ---------------------------------------------------------------------------
extern "C" void kernel_launch(void* const* d_in, const int* in_sizes, int n_in,
                              void* d_out, int out_size) {
    const float* x      = (const float*)d_in[0];
    const float* enc_w1 = (const float*)d_in[1];
    const float* enc_b1 = (const float*)d_in[2];
    const float* enc_w2 = (const float*)d_in[3];
    const float* enc_b2 = (const float*)d_in[4];
    const float* cb     = (const float*)d_in[5];
    const float* dec_w1 = (const float*)d_in[6];
    const float* dec_b1 = (const float*)d_in[7];
    const float* dec_w2 = (const float*)d_in[8];
    const float* dec_b2 = (const float*)d_in[9];

    float* out   = (float*)d_out;
    float* recon = out;
    float* quant = out + (size_t)NTOK * HDIM;
    float* tokf  = quant + (size_t)NTOK * HR;
    float* lossf = tokf + NTOK;

    void* p;
    cudaGetSymbolAddress(&p, g_h);     float*  h    = (float*)p;
    cudaGetSymbolAddress(&p, g_z);     float*  z    = (float*)p;
    cudaGetSymbolAddress(&p, g_h2);    float*  h2   = (float*)p;
    cudaGetSymbolAddress(&p, g_idx);   int*    idx  = (int*)p;
    cudaGetSymbolAddress(&p, g_cnorm); float*  cn   = (float*)p;
    cudaGetSymbolAddress(&p, g_part);  double* part = (double*)p;

    cnorm_kernel<<<CNUM, 128>>>(cb, cn);

    // encoder
    sgemm_bias<true ><<<dim3(HDIM / BN, NTOK / BM), NTHR>>>(x,  enc_w1, enc_b1, h, NTOK, HDIM, HDIM);
    sgemm_bias<false><<<dim3(HR   / BN, NTOK / BM), NTHR>>>(h,  enc_w2, enc_b2, z, NTOK, HR,   HDIM);

    // nearest codebook + gather + commit
    dist_argmin <<<NTOK / BM, NTHR>>>(z, cb, cn, idx);
    quant_commit<<<NTOK, 128>>>(z, cb, idx, quant, part);
    write_indices<<<NTOK / 256, 256>>>(idx, tokf);
    commit_reduce<<<1, 256>>>(part, lossf);

    // decoder
    sgemm_bias<true ><<<dim3(HDIM / BN, NTOK / BM), NTHR>>>(quant, dec_w1, dec_b1, h2,   NTOK, HDIM, HR);
    sgemm_bias<false><<<dim3(HDIM / BN, NTOK / BM), NTHR>>>(h2,    dec_w2, dec_b2, recon, NTOK, HDIM, HDIM);
}

// round 4
// speedup vs baseline: 1.0002x; 1.0002x over previous
#include <cuda_runtime.h>
#include <cstdint>

// ---------------------------------------------------------------------------
// QuantizedTokenizer: VQ-VAE tokenizer, fp32 with packed FFMA2 (fma.rn.f32x2).
//   B=32, Q=1024, H=1024, HR=512, C=4096, N = B*Q = 32768
// Outputs (flattened, float32, reference return order):
//   recon        [N,H]   @ 0
//   quantized_st [N,HR]  @ 33554432
//   token_index  [N]     @ 50331648 (as float)
//   commit_loss  [1]     @ 50364416
// ---------------------------------------------------------------------------

constexpr int NTOK = 32768;
constexpr int HDIM = 1024;
constexpr int HR   = 512;
constexpr int CNUM = 4096;

constexpr int BM = 128, BN = 128, BK = 16, NTHR = 256;

// Scratch (no allocation allowed -> __device__ globals)
__device__ float  g_h [(size_t)NTOK * HDIM];
__device__ float  g_z [(size_t)NTOK * HR];
__device__ float  g_h2[(size_t)NTOK * HDIM];
__device__ int    g_idx[NTOK];
__device__ float  g_cnorm[CNUM];
__device__ double g_part[NTOK];

// ---------------------------------------------------------------------------
// codebook row norms: ||c||^2
// ---------------------------------------------------------------------------
__global__ void cnorm_kernel(const float* __restrict__ cb, float* __restrict__ cn) {
    int c = blockIdx.x;
    const float* row = cb + (size_t)c * HR;
    float s = 0.f;
    for (int k = threadIdx.x; k < HR; k += 128) { float v = row[k]; s += v * v; }
    __shared__ float sh[128];
    sh[threadIdx.x] = s; __syncthreads();
    for (int o = 64; o > 0; o >>= 1) {
        if (threadIdx.x < o) sh[threadIdx.x] += sh[threadIdx.x + o];
        __syncthreads();
    }
    if (threadIdx.x == 0) cn[c] = sh[0];
}

// ---------------------------------------------------------------------------
// Packed f32x2 helpers (sm_103a FFMA2 path; bit-identical to scalar FFMA).
// ---------------------------------------------------------------------------
__device__ __forceinline__ unsigned long long splat_f32x2(float a) {
    unsigned long long r;
    asm("mov.b64 %0, {%1, %1};" : "=l"(r) : "f"(a));
    return r;
}
__device__ __forceinline__ void fma_f32x2(unsigned long long& acc,
                                          unsigned long long a, unsigned long long b) {
    asm("fma.rn.f32x2 %0, %1, %2, %0;" : "+l"(acc) : "l"(a), "l"(b));
}
__device__ __forceinline__ void unpack_f32x2(unsigned long long v, float& lo, float& hi) {
    asm("mov.b64 {%0, %1}, %2;" : "=f"(lo), "=f"(hi) : "l"(v));
}

// ---------------------------------------------------------------------------
// Micro-kernel (shared by sgemm and dist_argmin).
// Thread (ty 0..15, tx 0..15) owns rows {ty*4+i, 64+ty*4+i} and
// cols {tx*4+j, 64+tx*4+j}. All smem reads are LDS.128; B pairs are taken
// directly as f32x2 lanes; inner product runs on FFMA2 (32 instr/k-step).
// acc2[i][jp]: rows i (0..7 as above), col-pair jp -> cols
//   jp<2 : tx*4 + 2*jp + {0,1} ; jp>=2 : 64 + tx*4 + 2*(jp-2) + {0,1}
// ---------------------------------------------------------------------------
struct Frag { float4 a0, a1, b0, b1; };  // gmem staging registers

__device__ __forceinline__ void mm_step(const float (*As)[BM], const float (*Bs)[BN],
                                        int ty, int tx,
                                        unsigned long long acc2[8][4]) {
    #pragma unroll
    for (int k = 0; k < BK; k++) {
        float a[8];
        *reinterpret_cast<float4*>(&a[0]) = *reinterpret_cast<const float4*>(&As[k][ty * 4]);
        *reinterpret_cast<float4*>(&a[4]) = *reinterpret_cast<const float4*>(&As[k][64 + ty * 4]);
        unsigned long long b2[4];
        {
            ulonglong2 t0 = *reinterpret_cast<const ulonglong2*>(&Bs[k][tx * 4]);
            ulonglong2 t1 = *reinterpret_cast<const ulonglong2*>(&Bs[k][64 + tx * 4]);
            b2[0] = t0.x; b2[1] = t0.y; b2[2] = t1.x; b2[3] = t1.y;
        }
        #pragma unroll
        for (int i = 0; i < 8; i++) {
            unsigned long long ap = splat_f32x2(a[i]);
            #pragma unroll
            for (int jp = 0; jp < 4; jp++)
                fma_f32x2(acc2[i][jp], ap, b2[jp]);
        }
    }
}

// A-tile gmem load: 128 rows x 16 k, float4 along K; 2 vec4/thread.
__device__ __forceinline__ void load_a(const float* __restrict__ A, int row0, int K,
                                       int k0, int tid, float4& v0, float4& v1) {
    int r = tid >> 2, c = (tid & 3) * 4;
    v0 = *reinterpret_cast<const float4*>(&A[(size_t)(row0 + r) * K + k0 + c]);
    v1 = *reinterpret_cast<const float4*>(&A[(size_t)(row0 + r + 64) * K + k0 + c]);
}
__device__ __forceinline__ void store_a(float (*As)[BM], int tid, float4 v0, float4 v1) {
    int r = tid >> 2, c = (tid & 3) * 4;
    As[c + 0][r] = v0.x; As[c + 1][r] = v0.y; As[c + 2][r] = v0.z; As[c + 3][r] = v0.w;
    As[c + 0][r + 64] = v1.x; As[c + 1][r + 64] = v1.y;
    As[c + 2][r + 64] = v1.z; As[c + 3][r + 64] = v1.w;
}

// B-tile (row-major W[K,N]) gmem load: 16 k x 128 cols, float4 along N.
__device__ __forceinline__ void load_b_rowmajor(const float* __restrict__ W, int col0, int N,
                                                int k0, int tid, float4& v0, float4& v1) {
    int r = tid >> 5, c = (tid & 31) * 4;
    v0 = *reinterpret_cast<const float4*>(&W[(size_t)(k0 + r) * N + col0 + c]);
    v1 = *reinterpret_cast<const float4*>(&W[(size_t)(k0 + r + 8) * N + col0 + c]);
}
__device__ __forceinline__ void store_b_rowmajor(float (*Bs)[BN], int tid, float4 v0, float4 v1) {
    int r = tid >> 5, c = (tid & 31) * 4;
    *reinterpret_cast<float4*>(&Bs[r][c]) = v0;
    *reinterpret_cast<float4*>(&Bs[r + 8][c]) = v1;
}

// Codebook tile (CB[C,HR], need Bs[k][c] = CB[c0+c][k0+k]): transpose on store.
__device__ __forceinline__ void load_b_trans(const float* __restrict__ CB, int c0,
                                             int k0, int tid, float4& v0, float4& v1) {
    int r = tid >> 2, c = (tid & 3) * 4;   // r = codeword in tile, c = k offset
    v0 = *reinterpret_cast<const float4*>(&CB[(size_t)(c0 + r) * HR + k0 + c]);
    v1 = *reinterpret_cast<const float4*>(&CB[(size_t)(c0 + r + 64) * HR + k0 + c]);
}
__device__ __forceinline__ void store_b_trans(float (*Bs)[BN], int tid, float4 v0, float4 v1) {
    int r = tid >> 2, c = (tid & 3) * 4;
    Bs[c + 0][r] = v0.x; Bs[c + 1][r] = v0.y; Bs[c + 2][r] = v0.z; Bs[c + 3][r] = v0.w;
    Bs[c + 0][r + 64] = v1.x; Bs[c + 1][r + 64] = v1.y;
    Bs[c + 2][r + 64] = v1.z; Bs[c + 3][r + 64] = v1.w;
}

// ---------------------------------------------------------------------------
// SGEMM: C = act(A[M,K] @ W[K,N] + bias), 128x128x16, double-buffered smem.
// ---------------------------------------------------------------------------
template <bool RELU>
__global__ void __launch_bounds__(NTHR, 2)
sgemm_bias(const float* __restrict__ A, const float* __restrict__ W,
           const float* __restrict__ bias, float* __restrict__ C,
           int M, int N, int K) {
    __shared__ __align__(16) float As[2][BK][BM];
    __shared__ __align__(16) float Bs[2][BK][BN];

    const int tid  = threadIdx.x;
    const int tx   = tid & 15;
    const int ty   = tid >> 4;
    const int row0 = blockIdx.y * BM;
    const int col0 = blockIdx.x * BN;

    unsigned long long acc2[8][4] = {};   // zero bits == (0.f, 0.f)
    Frag f;

    load_a(A, row0, K, 0, tid, f.a0, f.a1);
    load_b_rowmajor(W, col0, N, 0, tid, f.b0, f.b1);
    store_a(As[0], tid, f.a0, f.a1);
    store_b_rowmajor(Bs[0], tid, f.b0, f.b1);
    __syncthreads();

    int buf = 0;
    for (int k0 = BK; k0 <= K; k0 += BK) {
        if (k0 < K) {
            load_a(A, row0, K, k0, tid, f.a0, f.a1);
            load_b_rowmajor(W, col0, N, k0, tid, f.b0, f.b1);
        }
        mm_step(As[buf], Bs[buf], ty, tx, acc2);
        if (k0 < K) {
            store_a(As[buf ^ 1], tid, f.a0, f.a1);
            store_b_rowmajor(Bs[buf ^ 1], tid, f.b0, f.b1);
            __syncthreads();
            buf ^= 1;
        }
    }

    #pragma unroll
    for (int ih = 0; ih < 2; ih++) {
        #pragma unroll
        for (int i = 0; i < 4; i++) {
            int r = row0 + ih * 64 + ty * 4 + i;
            #pragma unroll
            for (int jh = 0; jh < 2; jh++) {
                int c = col0 + jh * 64 + tx * 4;
                float4 bv = *reinterpret_cast<const float4*>(&bias[c]);
                float4 v;
                unpack_f32x2(acc2[ih * 4 + i][jh * 2 + 0], v.x, v.y);
                unpack_f32x2(acc2[ih * 4 + i][jh * 2 + 1], v.z, v.w);
                v.x += bv.x; v.y += bv.y; v.z += bv.z; v.w += bv.w;
                if (RELU) {
                    v.x = fmaxf(v.x, 0.f); v.y = fmaxf(v.y, 0.f);
                    v.z = fmaxf(v.z, 0.f); v.w = fmaxf(v.w, 0.f);
                }
                *reinterpret_cast<float4*>(&C[(size_t)r * N + c]) = v;
            }
        }
    }
}

// ---------------------------------------------------------------------------
// Distance GEMM + fused argmin.
// d[n,c] = ||cb_c||^2 - 2 z_n.cb_c ; idx = argmin_c (first index on ties).
// Packed key (orderable_f32(d) << 32 | c) -> min == argmin with jnp tie-break.
// ---------------------------------------------------------------------------
__device__ __forceinline__ unsigned int f32_orderable(float f) {
    unsigned int u = __float_as_uint(f);
    return (u & 0x80000000u) ? ~u : (u | 0x80000000u);
}

__global__ void __launch_bounds__(NTHR, 2)
dist_argmin(const float* __restrict__ Z, const float* __restrict__ CB,
            const float* __restrict__ cn, int* __restrict__ out_idx) {
    __shared__ __align__(16) float As[2][BK][BM];
    __shared__ __align__(16) float Bs[2][BK][BN];
    __shared__ unsigned long long best[BM];

    const int tid  = threadIdx.x;
    const int tx   = tid & 15;
    const int ty   = tid >> 4;
    const int row0 = blockIdx.x * BM;

    for (int i = tid; i < BM; i += NTHR) best[i] = 0xFFFFFFFFFFFFFFFFull;

    unsigned long long mykey[8];
    #pragma unroll
    for (int i = 0; i < 8; i++) mykey[i] = 0xFFFFFFFFFFFFFFFFull;

    for (int c0 = 0; c0 < CNUM; c0 += BN) {
        unsigned long long acc2[8][4] = {};
        Frag f;
        load_a(Z, row0, HR, 0, tid, f.a0, f.a1);
        load_b_trans(CB, c0, 0, tid, f.b0, f.b1);
        __syncthreads();                       // protect prev iter's smem reads
        store_a(As[0], tid, f.a0, f.a1);
        store_b_trans(Bs[0], tid, f.b0, f.b1);
        __syncthreads();

        int buf = 0;
        for (int k0 = BK; k0 <= HR; k0 += BK) {
            if (k0 < HR) {
                load_a(Z, row0, HR, k0, tid, f.a0, f.a1);
                load_b_trans(CB, c0, k0, tid, f.b0, f.b1);
            }
            mm_step(As[buf], Bs[buf], ty, tx, acc2);
            if (k0 < HR) {
                store_a(As[buf ^ 1], tid, f.a0, f.a1);
                store_b_trans(Bs[buf ^ 1], tid, f.b0, f.b1);
                __syncthreads();
                buf ^= 1;
            }
        }

        // fold this 128-codeword tile into per-thread running min
        #pragma unroll
        for (int jh = 0; jh < 2; jh++) {
            #pragma unroll
            for (int jp = 0; jp < 2; jp++) {
                int c = c0 + jh * 64 + tx * 4 + jp * 2;
                float cn0 = __ldg(&cn[c]);
                float cn1 = __ldg(&cn[c + 1]);
                #pragma unroll
                for (int i = 0; i < 8; i++) {
                    float d0, d1;
                    unpack_f32x2(acc2[i][jh * 2 + jp], d0, d1);
                    d0 = cn0 - 2.0f * d0;
                    d1 = cn1 - 2.0f * d1;
                    unsigned long long k0v =
                        ((unsigned long long)f32_orderable(d0) << 32) | (unsigned)c;
                    unsigned long long k1v =
                        ((unsigned long long)f32_orderable(d1) << 32) | (unsigned)(c + 1);
                    if (k0v < mykey[i]) mykey[i] = k0v;
                    if (k1v < mykey[i]) mykey[i] = k1v;
                }
            }
        }
    }

    __syncthreads();                           // best[] init + last smem reads done
    #pragma unroll
    for (int ih = 0; ih < 2; ih++)
        #pragma unroll
        for (int i = 0; i < 4; i++)
            atomicMin(&best[ih * 64 + ty * 4 + i], mykey[ih * 4 + i]);
    __syncthreads();
    for (int i = tid; i < BM; i += NTHR)
        out_idx[row0 + i] = (int)(best[i] & 0xFFFFFFFFu);
}

// ---------------------------------------------------------------------------
// Gather quantized = codebook[idx] -> out; per-token commit partial (double)
// ---------------------------------------------------------------------------
__global__ void quant_commit(const float* __restrict__ Z, const float* __restrict__ CB,
                             const int* __restrict__ idx, float* __restrict__ out_q,
                             double* __restrict__ part) {
    int t = blockIdx.x;
    const float* cbrow = CB + (size_t)idx[t] * HR;
    const float* zrow  = Z + (size_t)t * HR;
    float* qrow        = out_q + (size_t)t * HR;
    double s = 0.0;
    for (int k = threadIdx.x; k < HR; k += 128) {
        float q = cbrow[k];
        float d = zrow[k] - q;
        qrow[k] = q;
        s += (double)d * (double)d;
    }
    __shared__ double sh[128];
    sh[threadIdx.x] = s; __syncthreads();
    for (int o = 64; o > 0; o >>= 1) {
        if (threadIdx.x < o) sh[threadIdx.x] += sh[threadIdx.x + o];
        __syncthreads();
    }
    if (threadIdx.x == 0) part[t] = sh[0];
}

__global__ void commit_reduce(const double* __restrict__ part, float* __restrict__ out) {
    __shared__ double sh[256];
    double s = 0.0;
    for (int i = threadIdx.x; i < NTOK; i += 256) s += part[i];
    sh[threadIdx.x] = s; __syncthreads();
    for (int o = 128; o > 0; o >>= 1) {
        if (threadIdx.x < o) sh[threadIdx.x] += sh[threadIdx.x + o];
        __syncthreads();
    }
    if (threadIdx.x == 0)
        out[0] = (float)(0.25 * sh[0] / ((double)NTOK * (double)HR));
}

__global__ void write_indices(const int* __restrict__ idx, float* __restrict__ out) {
    int i = blockIdx.x * blockDim.x + threadIdx.x;
    if (i < NTOK) out[i] = (float)idx[i];
}

// ---------------------------------------------------------------------------
extern "C" void kernel_launch(void* const* d_in, const int* in_sizes, int n_in,
                              void* d_out, int out_size) {
    const float* x      = (const float*)d_in[0];
    const float* enc_w1 = (const float*)d_in[1];
    const float* enc_b1 = (const float*)d_in[2];
    const float* enc_w2 = (const float*)d_in[3];
    const float* enc_b2 = (const float*)d_in[4];
    const float* cb     = (const float*)d_in[5];
    const float* dec_w1 = (const float*)d_in[6];
    const float* dec_b1 = (const float*)d_in[7];
    const float* dec_w2 = (const float*)d_in[8];
    const float* dec_b2 = (const float*)d_in[9];

    float* out   = (float*)d_out;
    float* recon = out;
    float* quant = out + (size_t)NTOK * HDIM;
    float* tokf  = quant + (size_t)NTOK * HR;
    float* lossf = tokf + NTOK;

    void* p;
    cudaGetSymbolAddress(&p, g_h);     float*  h    = (float*)p;
    cudaGetSymbolAddress(&p, g_z);     float*  z    = (float*)p;
    cudaGetSymbolAddress(&p, g_h2);    float*  h2   = (float*)p;
    cudaGetSymbolAddress(&p, g_idx);   int*    idx  = (int*)p;
    cudaGetSymbolAddress(&p, g_cnorm); float*  cn   = (float*)p;
    cudaGetSymbolAddress(&p, g_part);  double* part = (double*)p;

    cnorm_kernel<<<CNUM, 128>>>(cb, cn);

    // encoder
    sgemm_bias<true ><<<dim3(HDIM / BN, NTOK / BM), NTHR>>>(x,  enc_w1, enc_b1, h, NTOK, HDIM, HDIM);
    sgemm_bias<false><<<dim3(HR   / BN, NTOK / BM), NTHR>>>(h,  enc_w2, enc_b2, z, NTOK, HR,   HDIM);

    // nearest codebook + gather + commit
    dist_argmin <<<NTOK / BM, NTHR>>>(z, cb, cn, idx);
    quant_commit<<<NTOK, 128>>>(z, cb, idx, quant, part);
    write_indices<<<NTOK / 256, 256>>>(idx, tokf);
    commit_reduce<<<1, 256>>>(part, lossf);

    // decoder
    sgemm_bias<true ><<<dim3(HDIM / BN, NTOK / BM), NTHR>>>(quant, dec_w1, dec_b1, h2,   NTOK, HDIM, HR);
    sgemm_bias<false><<<dim3(HDIM / BN, NTOK / BM), NTHR>>>(h2,    dec_w2, dec_b2, recon, NTOK, HDIM, HDIM);
}